// round 1
// baseline (speedup 1.0000x reference)
#include <cuda_runtime.h>
#include <math.h>

#define B_DIM 2
#define S_DIM 2048
#define D_DIM 2048
#define H_DIM 16
#define DH    128
#define M_DIM (B_DIM * S_DIM)   // 4096 rows of x

// ---------------- scratch (device globals: no allocation allowed) ----------
__device__ float g_Q [(size_t)B_DIM * H_DIM * S_DIM * DH];  // [B,H,S,dh]
__device__ float g_K [(size_t)B_DIM * H_DIM * S_DIM * DH];
__device__ float g_V [(size_t)B_DIM * H_DIM * S_DIM * DH];
__device__ float g_O [(size_t)B_DIM * H_DIM * S_DIM * DH];
__device__ float g_O2[(size_t)M_DIM * D_DIM];               // [B,S,D]

// ---------------- tiled fp32 GEMM:  C = A @ W^T + bias ---------------------
// A: [M, K] row-major.  W: [N, K] row-major (so W^T column n = W row n).
// MODE 0: C row-major [M, N]   (final output projection)
// MODE 1: scatter into [B, H, S, dh] layout (QKV projections)
#define TILE_M 128
#define TILE_N 128
#define TILE_K 16

template <int MODE>
__global__ __launch_bounds__(256) void gemm_nt_kernel(
    const float* __restrict__ A,
    const float* __restrict__ W,
    const float* __restrict__ bias,
    float* __restrict__ C,
    int M, int N, int K)
{
    __shared__ float As[TILE_K][TILE_M];
    __shared__ float Bs[TILE_K][TILE_N];

    const int bm = blockIdx.y * TILE_M;
    const int bn = blockIdx.x * TILE_N;
    const int tid = threadIdx.x;
    const int tx = tid & 15;   // n direction (16)
    const int ty = tid >> 4;   // m direction (16)

    float acc[8][8];
#pragma unroll
    for (int i = 0; i < 8; ++i)
#pragma unroll
        for (int j = 0; j < 8; ++j) acc[i][j] = 0.f;

    for (int k0 = 0; k0 < K; k0 += TILE_K) {
        // load A tile and W tile (each 128x16 floats = 512 float4, 2 per thread)
#pragma unroll
        for (int i = 0; i < 2; ++i) {
            int f = tid * 2 + i;          // 0..511
            int r = f >> 2;               // 0..127
            int kc = (f & 3) * 4;         // 0,4,8,12
            float4 va = *(const float4*)(A + (size_t)(bm + r) * K + k0 + kc);
            As[kc + 0][r] = va.x; As[kc + 1][r] = va.y;
            As[kc + 2][r] = va.z; As[kc + 3][r] = va.w;
            float4 vb = *(const float4*)(W + (size_t)(bn + r) * K + k0 + kc);
            Bs[kc + 0][r] = vb.x; Bs[kc + 1][r] = vb.y;
            Bs[kc + 2][r] = vb.z; Bs[kc + 3][r] = vb.w;
        }
        __syncthreads();

#pragma unroll
        for (int k = 0; k < TILE_K; ++k) {
            float a[8], b[8];
            *(float4*)&a[0] = *(const float4*)&As[k][ty * 8];
            *(float4*)&a[4] = *(const float4*)&As[k][ty * 8 + 4];
            *(float4*)&b[0] = *(const float4*)&Bs[k][tx * 8];
            *(float4*)&b[4] = *(const float4*)&Bs[k][tx * 8 + 4];
#pragma unroll
            for (int i = 0; i < 8; ++i)
#pragma unroll
                for (int j = 0; j < 8; ++j)
                    acc[i][j] += a[i] * b[j];
        }
        __syncthreads();
    }

    // epilogue
#pragma unroll
    for (int i = 0; i < 8; ++i) {
        int mrow = bm + ty * 8 + i;
#pragma unroll
        for (int j = 0; j < 8; j += 4) {
            int n = bn + tx * 8 + j;
            float4 r;
            r.x = acc[i][j + 0] + bias[n + 0];
            r.y = acc[i][j + 1] + bias[n + 1];
            r.z = acc[i][j + 2] + bias[n + 2];
            r.w = acc[i][j + 3] + bias[n + 3];
            if (MODE == 0) {
                *(float4*)(C + (size_t)mrow * N + n) = r;
            } else {
                int h  = n >> 7;        // n / 128
                int dd = n & 127;       // n % 128
                int b  = mrow / S_DIM;
                int s  = mrow - b * S_DIM;
                *(float4*)(C + (((size_t)(b * H_DIM + h) * S_DIM + s) * DH + dd)) = r;
            }
        }
    }
}

// ---------------- causal flash attention (fp32) ----------------------------
// grid: (S/128 q-tiles, B*H).  1 thread = 1 query row. K/V tiles in smem.
#define BC 32

__global__ __launch_bounds__(128) void attn_kernel(
    const float* __restrict__ Q,
    const float* __restrict__ K,
    const float* __restrict__ V,
    float* __restrict__ O)
{
    __shared__ float Ks[BC][DH];
    __shared__ float Vs[BC][DH];

    const int bh = blockIdx.y;
    const int qt = gridDim.x - 1 - blockIdx.x;     // heavy tiles first
    const int row = qt * 128 + threadIdx.x;

    const float* Qb = Q + (size_t)bh * S_DIM * DH;
    const float* Kb = K + (size_t)bh * S_DIM * DH;
    const float* Vb = V + (size_t)bh * S_DIM * DH;
    float*       Ob = O + (size_t)bh * S_DIM * DH;

    const float scale = 0.08838834764831845f;      // 1/sqrt(128)

    float m = -1e30f, l = 0.f;
    float acc[DH];
#pragma unroll
    for (int d = 0; d < DH; ++d) acc[d] = 0.f;

    const int nkt = qt * 4 + 4;                    // causal: k <= max row in block
    for (int kt = 0; kt < nkt; ++kt) {
        const int kbase = kt * BC;
        // load K,V tiles: 32x128 floats each = 1024 float4, 8 per thread
#pragma unroll
        for (int i = 0; i < 8; ++i) {
            int f = threadIdx.x + i * 128;         // 0..1023
            int r = f >> 5;
            int c = (f & 31) * 4;
            *(float4*)&Ks[r][c] = *(const float4*)(Kb + (size_t)(kbase + r) * DH + c);
            *(float4*)&Vs[r][c] = *(const float4*)(Vb + (size_t)(kbase + r) * DH + c);
        }
        __syncthreads();

        if (row >= kbase) {
            float sc[BC];
#pragma unroll
            for (int j = 0; j < BC; ++j) sc[j] = 0.f;

            // scores: dot(q_row, k_j) over 128 dims, q streamed in 16-chunks
#pragma unroll
            for (int c0 = 0; c0 < DH; c0 += 16) {
                float q[16];
#pragma unroll
                for (int u = 0; u < 16; u += 4) {
                    float4 v = *(const float4*)(Qb + (size_t)row * DH + c0 + u);
                    q[u + 0] = v.x * scale; q[u + 1] = v.y * scale;
                    q[u + 2] = v.z * scale; q[u + 3] = v.w * scale;
                }
#pragma unroll
                for (int j = 0; j < BC; ++j) {
#pragma unroll
                    for (int u = 0; u < 16; ++u)
                        sc[j] += q[u] * Ks[j][c0 + u];
                }
            }

            // causal mask + online softmax (fully unrolled: no runtime reg idx)
            float mt = m;
#pragma unroll
            for (int j = 0; j < BC; ++j) {
                float v = (kbase + j <= row) ? sc[j] : -1e30f;
                mt = fmaxf(mt, v);
            }
            float corr = __expf(m - mt);
            m = mt;
            l *= corr;
#pragma unroll
            for (int d = 0; d < DH; ++d) acc[d] *= corr;

            float p[BC];
#pragma unroll
            for (int j = 0; j < BC; ++j) {
                p[j] = (kbase + j <= row) ? __expf(sc[j] - mt) : 0.f;
                l += p[j];
            }
#pragma unroll
            for (int j = 0; j < BC; ++j) {
#pragma unroll
                for (int d = 0; d < DH; ++d)
                    acc[d] += p[j] * Vs[j][d];
            }
        }
        __syncthreads();
    }

    const float inv = 1.f / l;
#pragma unroll
    for (int d = 0; d < DH; d += 4) {
        float4 o;
        o.x = acc[d + 0] * inv; o.y = acc[d + 1] * inv;
        o.z = acc[d + 2] * inv; o.w = acc[d + 3] * inv;
        *(float4*)(Ob + (size_t)row * DH + d) = o;
    }
}

// ---------------- [B,H,S,dh] -> [B,S,D] transpose --------------------------
__global__ __launch_bounds__(256) void transpose_kernel(
    const float* __restrict__ O, float* __restrict__ O2)
{
    size_t idx = (size_t)blockIdx.x * blockDim.x + threadIdx.x;  // float4 id
    int d4 = (int)(idx & 31);            // 32 float4 per (b,h,s) row
    int s  = (int)((idx >> 5) & 2047);
    int h  = (int)((idx >> 16) & 15);
    int b  = (int)(idx >> 20);
    float4 v = ((const float4*)O)[idx];
    ((float4*)O2)[((size_t)(b * S_DIM + s)) * (D_DIM / 4) + h * 32 + d4] = v;
}

// ---------------- launch ----------------------------------------------------
extern "C" void kernel_launch(void* const* d_in, const int* in_sizes, int n_in,
                              void* d_out, int out_size)
{
    const float* x  = (const float*)d_in[0];
    const float* Wq = (const float*)d_in[1];
    const float* bq = (const float*)d_in[2];
    const float* Wk = (const float*)d_in[3];
    const float* bk = (const float*)d_in[4];
    const float* Wv = (const float*)d_in[5];
    const float* bv = (const float*)d_in[6];
    const float* Wo = (const float*)d_in[7];
    const float* bo = (const float*)d_in[8];
    float* out = (float*)d_out;

    float *qp, *kp, *vp, *op, *o2p;
    cudaGetSymbolAddress((void**)&qp,  g_Q);
    cudaGetSymbolAddress((void**)&kp,  g_K);
    cudaGetSymbolAddress((void**)&vp,  g_V);
    cudaGetSymbolAddress((void**)&op,  g_O);
    cudaGetSymbolAddress((void**)&o2p, g_O2);

    dim3 gg(D_DIM / TILE_N, M_DIM / TILE_M);   // (16, 32)
    gemm_nt_kernel<1><<<gg, 256>>>(x, Wq, bq, qp, M_DIM, D_DIM, D_DIM);
    gemm_nt_kernel<1><<<gg, 256>>>(x, Wk, bk, kp, M_DIM, D_DIM, D_DIM);
    gemm_nt_kernel<1><<<gg, 256>>>(x, Wv, bv, vp, M_DIM, D_DIM, D_DIM);

    dim3 ga(S_DIM / 128, B_DIM * H_DIM);       // (16, 32)
    attn_kernel<<<ga, 128>>>(qp, kp, vp, op);

    transpose_kernel<<<(B_DIM * H_DIM * S_DIM * DH / 4) / 256, 256>>>(op, o2p);

    gemm_nt_kernel<0><<<gg, 256>>>(o2p, Wo, bo, out, M_DIM, D_DIM, D_DIM);
}